// round 6
// baseline (speedup 1.0000x reference)
#include <cuda_runtime.h>
#include <cstdint>
#include <math.h>

// ---------------------------------------------------------------------------
// NNLS PGD step via tf32 mma.sync, 4-stage cp.async pipeline, 64x64 warp tile:
//   D     = (th1 - I) @ Y          (identity subtracted in-smem on diag tiles)
//   new_X = relu(D + Y + weight)   (exact fp32 identity term re-added)
//   Y_new = new_X + (k-1)/(k+2) * (new_X - X_old)
// out: [ Y_new (K*B) | new_X (K*B) | k+1 (1) | weight (K*B) ]
// ---------------------------------------------------------------------------

#define BM 128
#define BN 128
#define BK 16
#define THREADS 128
#define STAGES 4

#define A_PITCH 20     // floats per A smem row
#define B_PITCH 136    // floats per B smem row
#define A_STAGE (BM * A_PITCH)          // 2560 floats
#define B_STAGE (BK * B_PITCH)          // 2176 floats
#define B_BASE  (STAGES * A_STAGE)
#define SMEM_FLOATS (B_BASE + STAGES * B_STAGE)
#define SMEM_BYTES  (SMEM_FLOATS * 4)   // 75776 B

#define CP_ASYNC16(dst_u32, src_ptr) \
    asm volatile("cp.async.cg.shared.global [%0], [%1], 16;" :: "r"(dst_u32), "l"(src_ptr))
#define CP_COMMIT() asm volatile("cp.async.commit_group;")
#define CP_WAIT2()  asm volatile("cp.async.wait_group 2;")
#define CP_WAIT0()  asm volatile("cp.async.wait_group 0;")

#define MMA_TF32(c, a, b) \
    asm volatile("mma.sync.aligned.m16n8k8.row.col.f32.tf32.tf32.f32 " \
        "{%0,%1,%2,%3}, {%4,%5,%6,%7}, {%8,%9}, {%0,%1,%2,%3};" \
        : "+f"((c)[0]), "+f"((c)[1]), "+f"((c)[2]), "+f"((c)[3]) \
        : "r"((a)[0]), "r"((a)[1]), "r"((a)[2]), "r"((a)[3]), \
          "r"((b)[0]), "r"((b)[1]))

__global__ __launch_bounds__(THREADS, 2)
void nnls_mma_kernel(const float* __restrict__ A,    // th1 [Kd,Kd]
                     const float* __restrict__ Y,    // [Kd,N]
                     const float* __restrict__ Xold, // [Kd,N]
                     const int*   __restrict__ kptr,
                     const float* __restrict__ W,    // [Kd,N]
                     float*       __restrict__ out,
                     int Kd, int N)
{
    extern __shared__ float smem[];

    const int tid    = threadIdx.x;
    const int wid    = tid >> 5;
    const int lane   = tid & 31;
    const int lr     = lane >> 2;     // 0..7
    const int lq     = lane & 3;      // 0..3
    const int warp_m = wid & 1;       // 2 warps along M (64 rows each)
    const int warp_n = wid >> 1;      // 2 warps along N (64 cols each)
    const int m0     = blockIdx.x * BM;
    const int n0     = blockIdx.y * BN;
    const int NS     = Kd / BK;       // 64

    // cp.async coords: A 512 float4 / 128 thr = 4 each; B likewise
    const int arow0 = tid >> 2,  ac0 = tid & 3;    // rows arow0 + 32*i
    const int bk0   = tid >> 5,  bn0 = tid & 31;   // k-rows bk0 + 4*i

    const float* srcA = A + (long long)(m0 + arow0) * Kd + ac0 * 4;
    const float* srcB = Y + (long long)bk0 * N + n0 + bn0 * 4;
    const long long strideA32 = (long long)32 * Kd;
    const long long strideB4  = (long long)4 * N;

    auto issue_tile = [&](int t) {
        const int stg = t & (STAGES - 1);
        const int k0  = t * BK;
        float* as = smem + stg * A_STAGE;
        float* bs = smem + B_BASE + stg * B_STAGE;
        #pragma unroll
        for (int i = 0; i < 4; i++)
            CP_ASYNC16((uint32_t)__cvta_generic_to_shared(
                           as + (arow0 + 32 * i) * A_PITCH + ac0 * 4),
                       srcA + k0 + strideA32 * i);
        #pragma unroll
        for (int i = 0; i < 4; i++)
            CP_ASYNC16((uint32_t)__cvta_generic_to_shared(
                           bs + (bk0 + 4 * i) * B_PITCH + bn0 * 4),
                       srcB + (long long)k0 * N + strideB4 * i);
        CP_COMMIT();
    };

    float acc[4][8][4] = {};

    // ---- prologue: 3 tiles in flight ----
    issue_tile(0);
    issue_tile(1);
    issue_tile(2);

    for (int t = 0; t < NS; ++t) {
        const int stg = t & (STAGES - 1);
        CP_WAIT2();             // tile t resident (t+1, t+2 may be pending)
        __syncthreads();

        float* a_t = smem + stg * A_STAGE;
        float* b_t = smem + B_BASE + stg * B_STAGE;

        // identity subtraction on diagonal tiles (uniform branch per CTA)
        const int k0 = t * BK;
        if (k0 >= m0 && k0 < m0 + BM) {
            if (tid < BK) a_t[(k0 - m0 + tid) * A_PITCH + tid] -= 1.0f;
            __syncthreads();
        }

        if (t + 3 < NS) issue_tile(t + 3);

        #pragma unroll
        for (int kk = 0; kk < 2; kk++) {
            const int kb = kk * 8;
            uint32_t bfr[8][2], afr[4][4];
            #pragma unroll
            for (int nt = 0; nt < 8; nt++) {
                const float* bp = b_t + (kb + lq) * B_PITCH + warp_n * 64 + nt * 8 + lr;
                bfr[nt][0] = __float_as_uint(bp[0]);
                bfr[nt][1] = __float_as_uint(bp[4 * B_PITCH]);
            }
            #pragma unroll
            for (int mt = 0; mt < 4; mt++) {
                const float* ap = a_t + (warp_m * 64 + mt * 16 + lr) * A_PITCH + kb + lq;
                afr[mt][0] = __float_as_uint(ap[0]);
                afr[mt][1] = __float_as_uint(ap[8 * A_PITCH]);
                afr[mt][2] = __float_as_uint(ap[4]);
                afr[mt][3] = __float_as_uint(ap[8 * A_PITCH + 4]);
            }
            #pragma unroll
            for (int mt = 0; mt < 4; mt++)
                #pragma unroll
                for (int nt = 0; nt < 8; nt++)
                    MMA_TF32(acc[mt][nt], afr[mt], bfr[nt]);
        }
        __syncthreads();
    }
    CP_WAIT0();

    // ---------------- fused epilogue ----------------
    const long long KN = (long long)Kd * N;
    const float kf  = (float)kptr[0];
    const float mom = (kf - 1.0f) / (kf + 2.0f);

    #pragma unroll
    for (int mt = 0; mt < 4; mt++) {
        #pragma unroll
        for (int i = 0; i < 2; i++) {
            const int row = m0 + warp_m * 64 + mt * 16 + lr + i * 8;
            #pragma unroll
            for (int nt = 0; nt < 8; nt++) {
                const int col = n0 + warp_n * 64 + nt * 8 + lq * 2;
                const long long gi = (long long)row * N + col;
                float2 y2  = *reinterpret_cast<const float2*>(&Y[gi]);
                float2 w2  = *reinterpret_cast<const float2*>(&W[gi]);
                float2 xo2 = *reinterpret_cast<const float2*>(&Xold[gi]);
                float d0 = acc[mt][nt][i * 2 + 0] + y2.x + w2.x;
                float d1 = acc[mt][nt][i * 2 + 1] + y2.y + w2.y;
                float nx0 = fmaxf(d0, 0.0f);
                float nx1 = fmaxf(d1, 0.0f);
                float2 yn, nx;
                nx.x = nx0; nx.y = nx1;
                yn.x = nx0 + mom * (nx0 - xo2.x);
                yn.y = nx1 + mom * (nx1 - xo2.y);
                *reinterpret_cast<float2*>(&out[gi])      = yn;  // Y_new
                *reinterpret_cast<float2*>(&out[KN + gi]) = nx;  // new_X
                out[2 * KN + 1 + gi]     = w2.x;                 // weight copy
                out[2 * KN + 1 + gi + 1] = w2.y;
            }
        }
    }
    if (m0 == 0 && n0 == 0 && tid == 0) out[2 * KN] = kf + 1.0f;
}

extern "C" void kernel_launch(void* const* d_in, const int* in_sizes, int n_in,
                              void* d_out, int out_size)
{
    const float* th1  = (const float*)d_in[0];
    const float* Y    = (const float*)d_in[1];
    const float* Xold = (const float*)d_in[2];
    const int*   kptr = (const int*)  d_in[3];
    const float* W    = (const float*)d_in[4];
    float* out = (float*)d_out;

    int Kd = (int)lround(sqrt((double)in_sizes[0]));
    int N  = in_sizes[1] / Kd;

    static int smem_set = 0;
    if (!smem_set) {
        cudaFuncSetAttribute(nnls_mma_kernel,
                             cudaFuncAttributeMaxDynamicSharedMemorySize, SMEM_BYTES);
        smem_set = 1;
    }

    dim3 grid(Kd / BM, N / BN);   // (8, 64)
    nnls_mma_kernel<<<grid, THREADS, SMEM_BYTES>>>(th1, Y, Xold, kptr, W, out, Kd, N);
}

// round 8
// speedup vs baseline: 1.6538x; 1.6538x over previous
#include <cuda_runtime.h>
#include <cuda_bf16.h>
#include <cstdint>
#include <math.h>

// ---------------------------------------------------------------------------
// NNLS PGD step, bf16 mma.sync m16n8k16 with exact identity split:
//   pre-pass:  Abf = bf16(th1 - I) k-packed;  Ybf = bf16(Y) k-packed
//   D     = Abf @ Ybf              (tensor cores; tiny operands -> tiny error)
//   new_X = relu(D + Y + weight)   (exact fp32 identity term)
//   Y_new = new_X + (k-1)/(k+2) * (new_X - X_old)
// out: [ Y_new (K*B) | new_X (K*B) | k+1 (1) | weight (K*B) ]
// ---------------------------------------------------------------------------

#define KD 1024
#define NB 8192
#define BM 128
#define BN 128
#define BK 16
#define THREADS 256
#define STAGES 4

// packed layouts: [kt][row][16] bf16, row stride 32 B
__device__ __nv_bfloat16 g_Abf[KD * KD];
__device__ __nv_bfloat16 g_Ybf[KD * NB];

#define CP_ASYNC16(dst_u32, src_ptr) \
    asm volatile("cp.async.cg.shared.global [%0], [%1], 16;" :: "r"(dst_u32), "l"(src_ptr))
#define CP_COMMIT() asm volatile("cp.async.commit_group;")
#define CP_WAIT2()  asm volatile("cp.async.wait_group 2;")

#define MMA_BF16(c, a, b) \
    asm volatile("mma.sync.aligned.m16n8k16.row.col.f32.bf16.bf16.f32 " \
        "{%0,%1,%2,%3}, {%4,%5,%6,%7}, {%8,%9}, {%0,%1,%2,%3};" \
        : "+f"((c)[0]), "+f"((c)[1]), "+f"((c)[2]), "+f"((c)[3]) \
        : "r"((a)[0]), "r"((a)[1]), "r"((a)[2]), "r"((a)[3]), \
          "r"((b)[0]), "r"((b)[1]))

// ---------------- pre-pass: A' = bf16(th1 - I), k-packed ----------------
__global__ void convA(const float* __restrict__ A)
{
    int idx = blockIdx.x * blockDim.x + threadIdx.x;    // KD*KD/8 chunks
    int m  = idx >> 7;
    int k0 = (idx & 127) * 8;
    float4 v0 = *reinterpret_cast<const float4*>(&A[(long long)m * KD + k0]);
    float4 v1 = *reinterpret_cast<const float4*>(&A[(long long)m * KD + k0 + 4]);
    if (m - k0 >= 0 && m - k0 < 8) {
        float* f = (m - k0 < 4) ? &v0.x : &v1.x;
        f[(m - k0) & 3] -= 1.0f;
    }
    uint32_t u[4];
    { __nv_bfloat162 p = __floats2bfloat162_rn(v0.x, v0.y); u[0] = *reinterpret_cast<uint32_t*>(&p); }
    { __nv_bfloat162 p = __floats2bfloat162_rn(v0.z, v0.w); u[1] = *reinterpret_cast<uint32_t*>(&p); }
    { __nv_bfloat162 p = __floats2bfloat162_rn(v1.x, v1.y); u[2] = *reinterpret_cast<uint32_t*>(&p); }
    { __nv_bfloat162 p = __floats2bfloat162_rn(v1.z, v1.w); u[3] = *reinterpret_cast<uint32_t*>(&p); }
    int kt = k0 >> 4, kk = k0 & 15;
    *reinterpret_cast<uint4*>(&g_Abf[(long long)kt * (KD * 16) + m * 16 + kk]) =
        make_uint4(u[0], u[1], u[2], u[3]);
}

// ---------------- pre-pass: Y' = bf16(Y), transposed to [kt][n][16] ------
__global__ void convY(const float* __restrict__ Y)
{
    __shared__ __nv_bfloat16 sm[128][18];
    const int t  = threadIdx.x;
    const int kt = blockIdx.y;
    const int nb = blockIdx.x;
    const int r  = t >> 4;          // 0..15  k within tile
    const int cg = t & 15;          // 16 col-groups of 8
    const float* src = Y + (long long)(kt * 16 + r) * NB + nb * 128 + cg * 8;
    float4 a = *reinterpret_cast<const float4*>(src);
    float4 b = *reinterpret_cast<const float4*>(src + 4);
    const int n = cg * 8;
    sm[n + 0][r] = __float2bfloat16_rn(a.x);
    sm[n + 1][r] = __float2bfloat16_rn(a.y);
    sm[n + 2][r] = __float2bfloat16_rn(a.z);
    sm[n + 3][r] = __float2bfloat16_rn(a.w);
    sm[n + 4][r] = __float2bfloat16_rn(b.x);
    sm[n + 5][r] = __float2bfloat16_rn(b.y);
    sm[n + 6][r] = __float2bfloat16_rn(b.z);
    sm[n + 7][r] = __float2bfloat16_rn(b.w);
    __syncthreads();
    const int nn = t >> 1, half = t & 1;
    uint32_t u[4];
    #pragma unroll
    for (int j = 0; j < 4; j++) {
        __nv_bfloat162 p;
        p.x = sm[nn][half * 8 + 2 * j];
        p.y = sm[nn][half * 8 + 2 * j + 1];
        u[j] = *reinterpret_cast<uint32_t*>(&p);
    }
    *reinterpret_cast<uint4*>(
        &g_Ybf[(long long)kt * (NB * 16) + (nb * 128 + nn) * 16 + half * 8]) =
        make_uint4(u[0], u[1], u[2], u[3]);
}

// ---------------- main GEMM ----------------
__global__ __launch_bounds__(THREADS, 2)
void nnls_bf16_kernel(const float* __restrict__ Y,
                      const float* __restrict__ Xold,
                      const int*   __restrict__ kptr,
                      const float* __restrict__ W,
                      float*       __restrict__ out,
                      int Kd, int N)
{
    __shared__ __align__(16) char sA[STAGES][BM * 32];   // 4KB/stage
    __shared__ __align__(16) char sB[STAGES][BN * 32];

    const int tid    = threadIdx.x;
    const int wid    = tid >> 5;
    const int lane   = tid & 31;
    const int lr     = lane >> 2;
    const int lq     = lane & 3;
    const int warp_m = wid & 3;       // 4 warps along M (32 rows)
    const int warp_n = wid >> 2;      // 2 warps along N (64 cols)
    const int m0     = blockIdx.x * BM;
    const int n0     = blockIdx.y * BN;
    const int NS     = Kd / BK;       // 64

    // cp.async: one 16B chunk of A and one of B per thread per tile
    const int crow = tid >> 1;        // 0..127
    const int cch  = tid & 1;         // chunk half
    const int csw  = cch ^ ((crow >> 2) & 1);
    const char* srcA = reinterpret_cast<const char*>(g_Abf)
                     + ((long long)(m0 + crow) * 32 + cch * 16);
    const char* srcB = reinterpret_cast<const char*>(g_Ybf)
                     + ((long long)(n0 + crow) * 32 + cch * 16);
    const uint32_t dstA = (uint32_t)__cvta_generic_to_shared(sA[0] + crow * 32 + csw * 16);
    const uint32_t dstB = (uint32_t)__cvta_generic_to_shared(sB[0] + crow * 32 + csw * 16);
    const long long tileA = (long long)Kd * 32;   // bytes per k-tile of A'
    const long long tileB = (long long)N  * 32;

    auto issue_tile = [&](int t) {
        const int stg = t & (STAGES - 1);
        CP_ASYNC16(dstA + stg * (BM * 32), srcA + (long long)t * tileA);
        CP_ASYNC16(dstB + stg * (BN * 32), srcB + (long long)t * tileB);
        CP_COMMIT();
    };

    float acc[2][8][4] = {};

    issue_tile(0);
    issue_tile(1);
    issue_tile(2);

    for (int t = 0; t < NS; ++t) {
        const int stg = t & (STAGES - 1);
        CP_WAIT2();
        __syncthreads();
        if (t + 3 < NS) issue_tile(t + 3);

        const char* a_t = sA[stg];
        const char* b_t = sB[stg];

        uint32_t bfr[8][2], afr[2][4];
        #pragma unroll
        for (int nt = 0; nt < 8; nt++) {
            const int n = warp_n * 64 + nt * 8 + lr;
            const char* bp = b_t + n * 32;
            const int off = (4 * lq) ^ (((n >> 2) & 1) << 4);
            bfr[nt][0] = *reinterpret_cast<const uint32_t*>(bp + off);
            bfr[nt][1] = *reinterpret_cast<const uint32_t*>(bp + (off ^ 16));
        }
        #pragma unroll
        for (int mt = 0; mt < 2; mt++) {
            const int row = warp_m * 32 + mt * 16 + lr;
            const char* ap = a_t + row * 32;
            const int off = (4 * lq) ^ (((row >> 2) & 1) << 4);
            afr[mt][0] = *reinterpret_cast<const uint32_t*>(ap + off);
            afr[mt][1] = *reinterpret_cast<const uint32_t*>(ap + 8 * 32 + off);
            afr[mt][2] = *reinterpret_cast<const uint32_t*>(ap + (off ^ 16));
            afr[mt][3] = *reinterpret_cast<const uint32_t*>(ap + 8 * 32 + (off ^ 16));
        }
        #pragma unroll
        for (int mt = 0; mt < 2; mt++)
            #pragma unroll
            for (int nt = 0; nt < 8; nt++)
                MMA_BF16(acc[mt][nt], afr[mt], bfr[nt]);
        __syncthreads();
    }

    // ---------------- fused epilogue ----------------
    const long long KN = (long long)Kd * N;
    const float kf  = (float)kptr[0];
    const float mom = (kf - 1.0f) / (kf + 2.0f);

    #pragma unroll
    for (int mt = 0; mt < 2; mt++) {
        #pragma unroll
        for (int i = 0; i < 2; i++) {
            const int row = m0 + warp_m * 32 + mt * 16 + lr + i * 8;
            #pragma unroll
            for (int nt = 0; nt < 8; nt++) {
                const int col = n0 + warp_n * 64 + nt * 8 + lq * 2;
                const long long gi = (long long)row * N + col;
                float2 y2  = *reinterpret_cast<const float2*>(&Y[gi]);
                float2 w2  = *reinterpret_cast<const float2*>(&W[gi]);
                float2 xo2 = *reinterpret_cast<const float2*>(&Xold[gi]);
                float d0 = acc[mt][nt][i * 2 + 0] + y2.x + w2.x;
                float d1 = acc[mt][nt][i * 2 + 1] + y2.y + w2.y;
                float nx0 = fmaxf(d0, 0.0f);
                float nx1 = fmaxf(d1, 0.0f);
                float2 yn, nx;
                nx.x = nx0; nx.y = nx1;
                yn.x = nx0 + mom * (nx0 - xo2.x);
                yn.y = nx1 + mom * (nx1 - xo2.y);
                *reinterpret_cast<float2*>(&out[gi])      = yn;  // Y_new
                *reinterpret_cast<float2*>(&out[KN + gi]) = nx;  // new_X
                out[2 * KN + 1 + gi]     = w2.x;                 // weight copy
                out[2 * KN + 1 + gi + 1] = w2.y;
            }
        }
    }
    if (m0 == 0 && n0 == 0 && tid == 0) out[2 * KN] = kf + 1.0f;
}

extern "C" void kernel_launch(void* const* d_in, const int* in_sizes, int n_in,
                              void* d_out, int out_size)
{
    const float* th1  = (const float*)d_in[0];
    const float* Y    = (const float*)d_in[1];
    const float* Xold = (const float*)d_in[2];
    const int*   kptr = (const int*)  d_in[3];
    const float* W    = (const float*)d_in[4];
    float* out = (float*)d_out;

    int Kd = (int)lround(sqrt((double)in_sizes[0]));   // 1024
    int N  = in_sizes[1] / Kd;                         // 8192

    convA<<<(KD * KD / 8) / 256, 256>>>(th1);
    convY<<<dim3(NB / 128, KD / 16), 256>>>(Y);

    dim3 grid(Kd / BM, N / BN);   // (8, 64)
    nnls_bf16_kernel<<<grid, THREADS>>>(Y, Xold, kptr, W, out, Kd, N);
}